// round 10
// baseline (speedup 1.0000x reference)
#include <cuda_runtime.h>
#include <cuda_bf16.h>

#define NUM_O 1024
#define THREADS 256
#define WARPS 8
#define BLOCKS_PER_SM 2
#define GRID_BLOCKS (148 * BLOCKS_PER_SM)
#define TOTAL_WARPS (GRID_BLOCKS * WARPS)
#define ROW_STRIDE (TOTAL_WARPS * 2)

__device__ __forceinline__ float ex2_(float x) {
    float y; asm("ex2.approx.ftz.f32 %0, %1;" : "=f"(y) : "f"(x)); return y;
}

// 4-coeff uniform-sigma fast path (verified R3-R9, rel_err ~2.6e-6):
//   c = exp(-2*ls)*log2e ; sg = -c*|mu|^2 ; s_k = c*(2*mu_k - 1) ; scx = -c
//   arg_true = sg + s0*x0+s1*x1+s2*x2 + scx*(xx-(x0+x1+x2))
// UNI: scx term is per-row constant -> cancels in normalization; remaining
// arg <= 0 for x,mu in [0,1]^3 (no overflow).
template<bool UNI>
__device__ __forceinline__ void run_rows2(
    const float* __restrict__ sg, const float* __restrict__ s0,
    const float* __restrict__ s1, const float* __restrict__ s2,
    const float* __restrict__ scx,
    const float* __restrict__ x, float* __restrict__ out,
    int rows, int gwarp, int lane)
{
    int row = gwarp * 2;
    if (row >= rows) return;

    // --- x prefetch pipeline: xc = current pair, loaded before loop ---
    int rB0 = (row + 1 < rows) ? (row + 1) : row;
    float xc[6];
    xc[0] = __ldg(&x[row*3+0]); xc[1] = __ldg(&x[row*3+1]); xc[2] = __ldg(&x[row*3+2]);
    xc[3] = __ldg(&x[rB0*3+0]); xc[4] = __ldg(&x[rB0*3+1]); xc[5] = __ldg(&x[rB0*3+2]);

    const int olane = lane * 4;

    for (; row < rows; row += ROW_STRIDE) {
        const int rowB = (row + 1 < rows) ? (row + 1) : row;

        // Issue next pair's x loads NOW; consumed next iteration.
        float xn[6];
        {
            int nr = row + ROW_STRIDE;
            if (nr < rows) {
                int nrB = (nr + 1 < rows) ? (nr + 1) : nr;
                xn[0] = __ldg(&x[nr*3+0]);  xn[1] = __ldg(&x[nr*3+1]);  xn[2] = __ldg(&x[nr*3+2]);
                xn[3] = __ldg(&x[nrB*3+0]); xn[4] = __ldg(&x[nrB*3+1]); xn[5] = __ldg(&x[nrB*3+2]);
            } else {
                xn[0]=xc[0]; xn[1]=xc[1]; xn[2]=xc[2]; xn[3]=xc[3]; xn[4]=xc[4]; xn[5]=xc[5];
            }
        }

        const float xa0 = xc[0], xa1 = xc[1], xa2 = xc[2];
        const float xb0 = xc[3], xb1 = xc[4], xb2 = xc[5];
        float sxa, sxb;
        if (!UNI) {
            sxa = (xa0*xa0 + xa1*xa1 + xa2*xa2) - (xa0 + xa1 + xa2);
            sxb = (xb0*xb0 + xb1*xb1 + xb2*xb2) - (xb0 + xb1 + xb2);
        }

        float ea[32], eb[32];
        float accA0 = 0.f, accA1 = 0.f, accB0 = 0.f, accB1 = 0.f;

        // --- coefficient double-buffer: load j+1 before j's math ---
        float4 G = *reinterpret_cast<const float4*>(sg + olane);
        float4 A = *reinterpret_cast<const float4*>(s0 + olane);
        float4 B = *reinterpret_cast<const float4*>(s1 + olane);
        float4 C = *reinterpret_cast<const float4*>(s2 + olane);
        float4 S;
        if (!UNI) S = *reinterpret_cast<const float4*>(scx + olane);

        #pragma unroll
        for (int j = 0; j < 8; j++) {
            float4 Gn, An, Bn, Cn, Sn;
            if (j < 7) {
                const int on = (j + 1) * 128 + olane;
                Gn = *reinterpret_cast<const float4*>(sg + on);
                An = *reinterpret_cast<const float4*>(s0 + on);
                Bn = *reinterpret_cast<const float4*>(s1 + on);
                Cn = *reinterpret_cast<const float4*>(s2 + on);
                if (!UNI) Sn = *reinterpret_cast<const float4*>(scx + on);
            }

            float a0 = G.x, a1 = G.y, a2 = G.z, a3 = G.w;
            float b0 = G.x, b1 = G.y, b2 = G.z, b3 = G.w;
            if (!UNI) {
                a0 = fmaf(S.x, sxa, a0); a1 = fmaf(S.y, sxa, a1);
                a2 = fmaf(S.z, sxa, a2); a3 = fmaf(S.w, sxa, a3);
                b0 = fmaf(S.x, sxb, b0); b1 = fmaf(S.y, sxb, b1);
                b2 = fmaf(S.z, sxb, b2); b3 = fmaf(S.w, sxb, b3);
            }
            a0 = fmaf(C.x, xa2, a0); a1 = fmaf(C.y, xa2, a1);
            a2 = fmaf(C.z, xa2, a2); a3 = fmaf(C.w, xa2, a3);
            b0 = fmaf(C.x, xb2, b0); b1 = fmaf(C.y, xb2, b1);
            b2 = fmaf(C.z, xb2, b2); b3 = fmaf(C.w, xb2, b3);
            a0 = fmaf(B.x, xa1, a0); a1 = fmaf(B.y, xa1, a1);
            a2 = fmaf(B.z, xa1, a2); a3 = fmaf(B.w, xa1, a3);
            b0 = fmaf(B.x, xb1, b0); b1 = fmaf(B.y, xb1, b1);
            b2 = fmaf(B.z, xb1, b2); b3 = fmaf(B.w, xb1, b3);
            a0 = fmaf(A.x, xa0, a0); a1 = fmaf(A.y, xa0, a1);
            a2 = fmaf(A.z, xa0, a2); a3 = fmaf(A.w, xa0, a3);
            b0 = fmaf(A.x, xb0, b0); b1 = fmaf(A.y, xb0, b1);
            b2 = fmaf(A.z, xb0, b2); b3 = fmaf(A.w, xb0, b3);

            const float va0 = ex2_(a0), va1 = ex2_(a1), va2 = ex2_(a2), va3 = ex2_(a3);
            const float vb0 = ex2_(b0), vb1 = ex2_(b1), vb2 = ex2_(b2), vb3 = ex2_(b3);
            ea[j*4+0] = va0; ea[j*4+1] = va1; ea[j*4+2] = va2; ea[j*4+3] = va3;
            eb[j*4+0] = vb0; eb[j*4+1] = vb1; eb[j*4+2] = vb2; eb[j*4+3] = vb3;
            accA0 += (va0 + va1); accA1 += (va2 + va3);
            accB0 += (vb0 + vb1); accB1 += (vb2 + vb3);

            if (j < 7) { G = Gn; A = An; B = Bn; C = Cn; if (!UNI) S = Sn; }
        }

        float accA = accA0 + accA1;
        float accB = accB0 + accB1;
        #pragma unroll
        for (int off = 16; off > 0; off >>= 1) {
            accA += __shfl_xor_sync(0xFFFFFFFFu, accA, off);
            accB += __shfl_xor_sync(0xFFFFFFFFu, accB, off);
        }
        const float rcpA = 1.0f / accA;
        const float rcpB = 1.0f / accB;

        float* orowA = out + (size_t)row * NUM_O + olane;
        #pragma unroll
        for (int j = 0; j < 8; j++) {
            float4 v;
            v.x = ea[j*4+0] * rcpA; v.y = ea[j*4+1] * rcpA;
            v.z = ea[j*4+2] * rcpA; v.w = ea[j*4+3] * rcpA;
            *reinterpret_cast<float4*>(orowA + j * 128) = v;
        }
        if (rowB != row) {
            float* orowB = out + (size_t)rowB * NUM_O + olane;
            #pragma unroll
            for (int j = 0; j < 8; j++) {
                float4 v;
                v.x = eb[j*4+0] * rcpB; v.y = eb[j*4+1] * rcpB;
                v.z = eb[j*4+2] * rcpB; v.w = eb[j*4+3] * rcpB;
                *reinterpret_cast<float4*>(orowB + j * 128) = v;
            }
        }

        xc[0]=xn[0]; xc[1]=xn[1]; xc[2]=xn[2]; xc[3]=xn[3]; xc[4]=xn[4]; xc[5]=xn[5];
    }
}

__global__ void __launch_bounds__(THREADS, BLOCKS_PER_SM)
gaussian_rbf_kernel(const float* __restrict__ x,
                    const float* __restrict__ mus,
                    const float* __restrict__ log_sigmas,
                    float* __restrict__ out,
                    int rows)
{
    __shared__ __align__(16) float sg[NUM_O];
    __shared__ __align__(16) float s0[NUM_O];
    __shared__ __align__(16) float s1[NUM_O];
    __shared__ __align__(16) float s2[NUM_O];
    __shared__ __align__(16) float scx[NUM_O];

    const float LOG2E = 1.4426950408889634f;
    const float ls0 = __ldg(&log_sigmas[0]);
    bool uni = true;

    for (int o = threadIdx.x; o < NUM_O; o += THREADS) {
        float ls = __ldg(&log_sigmas[o]);
        uni = uni && (ls == ls0);
        float m0 = mus[3*o + 0];
        float m1 = mus[3*o + 1];
        float m2 = mus[3*o + 2];
        float c = __expf(-2.0f * ls) * LOG2E;
        sg[o] = -c * (m0*m0 + m1*m1 + m2*m2);
        s0[o] = c * (2.0f * m0 - 1.0f);
        s1[o] = c * (2.0f * m1 - 1.0f);
        s2[o] = c * (2.0f * m2 - 1.0f);
        scx[o] = -c;
    }
    int uall = __syncthreads_and(uni ? 1 : 0);
    // No further block-wide synchronization: warps proceed independently.

    const int warp  = threadIdx.x >> 5;
    const int lane  = threadIdx.x & 31;
    const int gwarp = blockIdx.x * WARPS + warp;

    if (uall)
        run_rows2<true >(sg, s0, s1, s2, scx, x, out, rows, gwarp, lane);
    else
        run_rows2<false>(sg, s0, s1, s2, scx, x, out, rows, gwarp, lane);
}

extern "C" void kernel_launch(void* const* d_in, const int* in_sizes, int n_in,
                              void* d_out, int out_size) {
    const float* x          = (const float*)d_in[0];  // (B,S,3)
    const float* mus        = (const float*)d_in[1];  // (1024,3)
    const float* log_sigmas = (const float*)d_in[2];  // (1024,)
    float* out = (float*)d_out;

    const int rows = in_sizes[0] / 3;  // B*S
    gaussian_rbf_kernel<<<GRID_BLOCKS, THREADS>>>(x, mus, log_sigmas, out, rows);
}